// round 2
// baseline (speedup 1.0000x reference)
#include <cuda_runtime.h>
#include <math.h>

#define DZ 31

static constexpr long long S0  = 31LL * 256 * 256;
static constexpr long long S1  = 31LL * 128 * 128;
static constexpr long long S2L = 31LL * 64 * 64;

static constexpr long long O_CONV = 0;                      // conv output scratch (max 48*S0)
static constexpr long long O_FE   = O_CONV + 48 * S0;
static constexpr long long O_E0   = O_FE   + 16 * S0;
static constexpr long long O_E1   = O_E0   + 16 * S0;
static constexpr long long O_E2   = O_E1   + 32 * S1;
static constexpr long long O_E3   = O_E2   + 32 * S1;
static constexpr long long O_E4   = O_E3   + 64 * S2L;
static constexpr long long O_D0   = O_E4   + 64 * S2L;
static constexpr long long O_UP1  = O_D0   + 64 * S2L;
static constexpr long long O_D1   = O_UP1  + 64 * S1;
static constexpr long long O_TMP1 = O_D1   + 32 * S1;
static constexpr long long O_D2   = O_TMP1 + 32 * S1;
static constexpr long long O_UP0  = O_D2   + 32 * S1;
static constexpr long long O_D3   = O_UP0  + 32 * S0;
static constexpr long long O_D4   = O_D3   + 16 * S0;
static constexpr long long TOTAL  = O_D4   + 16 * S0;

__device__ float g_buf[TOTAL];

__device__ __forceinline__ float sigm(float x)  { return 1.0f / (1.0f + __expf(-x)); }
__device__ __forceinline__ float tanhfast(float x) { return 2.0f / (1.0f + __expf(-2.0f * x)) - 1.0f; }

// ---- f32x2 packed-math helpers (sm_103a) ----
__device__ __forceinline__ unsigned long long pk(float lo, float hi) {
    unsigned long long r;
    asm("mov.b64 %0, {%1, %2};" : "=l"(r) : "f"(lo), "f"(hi));
    return r;
}
__device__ __forceinline__ void upk(unsigned long long a, float& lo, float& hi) {
    asm("mov.b64 {%0, %1}, %2;" : "=f"(lo), "=f"(hi) : "l"(a));
}
__device__ __forceinline__ void ffma2(unsigned long long& acc, unsigned long long v, unsigned long long w) {
    asm("fma.rn.f32x2 %0, %1, %2, %0;" : "+l"(acc) : "l"(v), "l"(w));
}

// ============================================================================
// Direct conv3d 3x3x3, pad 1, H/W stride = STRIDE, FLIP=1 -> deconv.
// Block 16x8 = 128 threads. Each thread: 4 outputs in x  x  COPT channels.
// Output tile per block: 64 x 8 at one (co group, depth d).
// COPT==4 path: accumulators are f32x2 channel-pairs; weight pairs come
// directly from the two halves of an LDS.128; input scalar splatted once.
// ============================================================================
template <int COPT, int STRIDE, int FLIP>
__global__ void conv3d_kernel(const float* __restrict__ in, const float* __restrict__ w,
                              const float* __restrict__ bias, float* __restrict__ out,
                              int Ci, int Co, int Hin, int Win, int Hout, int Wout)
{
    constexpr int OX = 4;
    constexpr int TW = 64, TH = 8;
    constexpr int IWr = TW * STRIDE + 2;
    constexpr int IW  = (IWr + 3) & ~3;          // 68 (s1) / 132 (s2)
    constexpr int IH  = TH * STRIDE + 2;         // 10 / 18
    constexpr int NV  = (STRIDE == 1) ? 8 : 12;  // input floats loaded per tap-row
    constexpr int NS  = (STRIDE == 1) ? 6 : 10;  // splats actually used

    extern __shared__ float sm[];
    float* s_w  = sm;                      // Ci*27*COPT
    float* s_in = sm + Ci * 27 * COPT;     // 3*IH*IW

    const int tx  = threadIdx.x, ty = threadIdx.y;
    const int tid = ty * 16 + tx;
    const int d   = blockIdx.z % DZ;
    const int co0 = (blockIdx.z / DZ) * COPT;
    const int ox0 = blockIdx.x * TW;
    const int oy0 = blockIdx.y * TH;

    const int WCNT = Ci * 27 * COPT;
    for (int t = tid; t < WCNT; t += 128) {
        int j  = t % COPT;
        int r  = t / COPT;
        int k  = r % 27;
        int ci = r / 27;
        int kk = FLIP ? (26 - k) : k;
        s_w[t] = w[((long long)(co0 + j) * Ci + ci) * 27 + kk];
    }

    unsigned long long accp[OX][2];   // COPT==4 path: [x][co-pair]
    float accs[COPT][OX];             // scalar path (COPT != 4)
    if (COPT == 4) {
        unsigned long long b01 = pk(bias[co0], bias[co0 + 1]);
        unsigned long long b23 = pk(bias[co0 + 2], bias[co0 + 3]);
#pragma unroll
        for (int x = 0; x < OX; x++) { accp[x][0] = b01; accp[x][1] = b23; }
    } else {
#pragma unroll
        for (int j = 0; j < COPT; j++)
#pragma unroll
            for (int x = 0; x < OX; x++) accs[j][x] = bias[co0 + j];
    }

    const int gx0 = ox0 * STRIDE - 1;
    const int gy0 = oy0 * STRIDE - 1;
    const long long HWin = (long long)Hin * Win;

    for (int ci = 0; ci < Ci; ci++) {
        __syncthreads();
        const float* inc = in + (long long)ci * DZ * HWin;
        for (int t = tid; t < 3 * IH * IW; t += 128) {
            int kd = t / (IH * IW);
            int rr = (t / IW) % IH;
            int cc = t % IW;
            int gz = d - 1 + kd;
            int gy = gy0 + rr;
            int gx = gx0 + cc;
            float v = 0.0f;
            if (gz >= 0 && gz < DZ && (unsigned)gy < (unsigned)Hin && (unsigned)gx < (unsigned)Win)
                v = inc[(long long)gz * HWin + (long long)gy * Win + gx];
            s_in[t] = v;
        }
        __syncthreads();

        const float* swc = s_w + ci * 27 * COPT;
#pragma unroll
        for (int kd = 0; kd < 3; kd++) {
#pragma unroll
            for (int kh = 0; kh < 3; kh++) {
                const float* row = s_in + ((kd * IH) + ty * STRIDE + kh) * IW + tx * (OX * STRIDE);
                float vv[NV];
                *reinterpret_cast<float4*>(vv)     = *reinterpret_cast<const float4*>(row);
                *reinterpret_cast<float4*>(vv + 4) = *reinterpret_cast<const float4*>(row + 4);
                if (STRIDE == 2)
                    *reinterpret_cast<float4*>(vv + 8) = *reinterpret_cast<const float4*>(row + 8);

                if (COPT == 4) {
                    unsigned long long sv[NS];
#pragma unroll
                    for (int i = 0; i < NS; i++) sv[i] = pk(vv[i], vv[i]);
#pragma unroll
                    for (int kw = 0; kw < 3; kw++) {
                        const int k = (kd * 3 + kh) * 3 + kw;
                        const ulonglong2 wp = *reinterpret_cast<const ulonglong2*>(swc + k * 4);
#pragma unroll
                        for (int x = 0; x < OX; x++) {
                            const int ii = x * STRIDE + kw;
                            ffma2(accp[x][0], sv[ii], wp.x);
                            ffma2(accp[x][1], sv[ii], wp.y);
                        }
                    }
                } else {
#pragma unroll
                    for (int kw = 0; kw < 3; kw++) {
                        const int k = (kd * 3 + kh) * 3 + kw;
#pragma unroll
                        for (int j = 0; j < COPT; j++) {
                            const float wj = swc[k * COPT + j];
#pragma unroll
                            for (int x = 0; x < OX; x++)
                                accs[j][x] += vv[x * STRIDE + kw] * wj;
                        }
                    }
                }
            }
        }
    }

    const long long HWout = (long long)Hout * Wout;
    const int oy = oy0 + ty;
    const int oxb = ox0 + tx * OX;
    if (COPT == 4) {
        float o[4][OX];
#pragma unroll
        for (int x = 0; x < OX; x++) {
            upk(accp[x][0], o[0][x], o[1][x]);
            upk(accp[x][1], o[2][x], o[3][x]);
        }
#pragma unroll
        for (int j = 0; j < 4; j++) {
            float4 v4 = make_float4(o[j][0], o[j][1], o[j][2], o[j][3]);
            *reinterpret_cast<float4*>(out + ((long long)(co0 + j) * DZ + d) * HWout +
                                       (long long)oy * Wout + oxb) = v4;
        }
    } else {
#pragma unroll
        for (int j = 0; j < COPT; j++) {
            float4 v4 = make_float4(accs[j][0], accs[j][1], accs[j][2], accs[j][3]);
            *reinterpret_cast<float4*>(out + ((long long)(co0 + j) * DZ + d) * HWout +
                                       (long long)oy * Wout + oxb) = v4;
        }
    }
}

// ============================================================================
// fo_pool (QRNN): gates [2*ch][DZ][HW]. float2 per thread (2 indep chains).
// ============================================================================
__global__ void qrnn_kernel(const float* __restrict__ g, float* __restrict__ out,
                            int ch, long long HW, int reverse)
{
    long long H2 = HW / 2;
    long long idx = (long long)blockIdx.x * blockDim.x + threadIdx.x;
    if (idx >= (long long)ch * H2) return;
    int c = (int)(idx / H2);
    long long p = (idx % H2);
    const float2* zp = reinterpret_cast<const float2*>(g + (long long)c * DZ * HW) + p;
    const float2* fp = reinterpret_cast<const float2*>(g + (long long)(ch + c) * DZ * HW) + p;
    float2* op = reinterpret_cast<float2*>(out + (long long)c * DZ * HW) + p;
    float hx = 0.0f, hy = 0.0f;
    if (!reverse) {
        for (int t = 0; t < DZ; t++) {
            float2 z2 = zp[t * H2];
            float2 f2 = fp[t * H2];
            float fx = sigm(f2.x), fy = sigm(f2.y);
            hx = fx * hx + (1.0f - fx) * tanhfast(z2.x);
            hy = fy * hy + (1.0f - fy) * tanhfast(z2.y);
            op[t * H2] = make_float2(hx, hy);
        }
    } else {
        for (int t = DZ - 1; t >= 0; t--) {
            float2 z2 = zp[t * H2];
            float2 f2 = fp[t * H2];
            float fx = sigm(f2.x), fy = sigm(f2.y);
            hx = fx * hx + (1.0f - fx) * tanhfast(z2.x);
            hy = fy * hy + (1.0f - fy) * tanhfast(z2.y);
            op[t * H2] = make_float2(hx, hy);
        }
    }
}

// ============================================================================
// biQRNN: gates [3*ch][DZ][HW] (z,f1,f2); fwd writes, rev accumulates (+resid).
// ============================================================================
__global__ void biqrnn_kernel(const float* __restrict__ g, const float* __restrict__ resid,
                              float* __restrict__ out, int ch, long long HW)
{
    long long H2 = HW / 2;
    long long idx = (long long)blockIdx.x * blockDim.x + threadIdx.x;
    if (idx >= (long long)ch * H2) return;
    int c = (int)(idx / H2);
    long long p = (idx % H2);
    const float2* zp = reinterpret_cast<const float2*>(g + (long long)c * DZ * HW) + p;
    const float2* f1 = reinterpret_cast<const float2*>(g + (long long)(ch + c) * DZ * HW) + p;
    const float2* f2 = reinterpret_cast<const float2*>(g + (long long)(2 * ch + c) * DZ * HW) + p;
    float2* op = reinterpret_cast<float2*>(out + (long long)c * DZ * HW) + p;
    const float2* rp = resid ? (reinterpret_cast<const float2*>(resid + (long long)c * DZ * HW) + p)
                             : nullptr;
    float hx = 0.0f, hy = 0.0f;
    for (int t = 0; t < DZ; t++) {
        float2 z2 = zp[t * H2];
        float2 ff = f1[t * H2];
        float fx = sigm(ff.x), fy = sigm(ff.y);
        hx = fx * hx + (1.0f - fx) * tanhfast(z2.x);
        hy = fy * hy + (1.0f - fy) * tanhfast(z2.y);
        op[t * H2] = make_float2(hx, hy);
    }
    hx = 0.0f; hy = 0.0f;
    for (int t = DZ - 1; t >= 0; t--) {
        float2 z2 = zp[t * H2];
        float2 ff = f2[t * H2];
        float fx = sigm(ff.x), fy = sigm(ff.y);
        hx = fx * hx + (1.0f - fx) * tanhfast(z2.x);
        hy = fy * hy + (1.0f - fy) * tanhfast(z2.y);
        float2 cur = op[t * H2];
        float rx = 0.0f, ry = 0.0f;
        if (rp) { float2 r2 = rp[t * H2]; rx = r2.x; ry = r2.y; }
        op[t * H2] = make_float2(cur.x + hx + rx, cur.y + hy + ry);
    }
}

// 2x nearest upsample of (a+b); float4-vectorized over output.
__global__ void upadd_kernel(const float* __restrict__ a, const float* __restrict__ b,
                             float* __restrict__ out, int ch, int Hs, int Ws)
{
    long long N4 = (long long)ch * DZ * 4LL * Hs * Ws / 4;
    long long i = (long long)blockIdx.x * blockDim.x + threadIdx.x;
    if (i >= N4) return;
    int Wd4 = (2 * Ws) / 4;
    int x4 = (int)(i % Wd4);
    long long r = i / Wd4;
    int y = (int)(r % (2 * Hs));
    r /= (2 * Hs);   // r = c*DZ + d
    long long src = r * ((long long)Hs * Ws) + (long long)(y >> 1) * Ws + x4 * 2;
    float2 av = *reinterpret_cast<const float2*>(a + src);
    float2 bv = *reinterpret_cast<const float2*>(b + src);
    float sx = av.x + bv.x, sy = av.y + bv.y;
    reinterpret_cast<float4*>(out)[i] = make_float4(sx, sx, sy, sy);
}

__global__ void add_kernel(const float* __restrict__ a, const float* __restrict__ b,
                           float* __restrict__ o, long long n4)
{
    long long i = (long long)blockIdx.x * blockDim.x + threadIdx.x;
    if (i >= n4) return;
    float4 av = reinterpret_cast<const float4*>(a)[i];
    float4 bv = reinterpret_cast<const float4*>(b)[i];
    reinterpret_cast<float4*>(o)[i] = make_float4(av.x + bv.x, av.y + bv.y, av.z + bv.z, av.w + bv.w);
}

// ============================================================================
// Host-side launch helpers
// ============================================================================
template <int COPT, int STRIDE, int FLIP>
static void conv_l(const float* in, const float* w, const float* b, float* out,
                   int Ci, int Co, int Hin, int Win)
{
    int Hout = Hin / STRIDE, Wout = Win / STRIDE;
    constexpr int IWr = 64 * STRIDE + 2;
    constexpr int IW  = (IWr + 3) & ~3;
    constexpr int IH  = 8 * STRIDE + 2;
    dim3 grid(Wout / 64, Hout / 8, (Co / COPT) * DZ);
    size_t smem = (size_t)(Ci * 27 * COPT + 3 * IH * IW) * sizeof(float);
    conv3d_kernel<COPT, STRIDE, FLIP><<<grid, dim3(16, 8), smem>>>(
        in, w, b, out, Ci, Co, Hin, Win, Hout, Wout);
}

static void qrnn_l(const float* g, float* out, int ch, long long HW, int reverse)
{
    long long n = (long long)ch * HW / 2;
    qrnn_kernel<<<(unsigned)((n + 255) / 256), 256>>>(g, out, ch, HW, reverse);
}

static void biqrnn_l(const float* g, const float* resid, float* out, int ch, long long HW)
{
    long long n = (long long)ch * HW / 2;
    biqrnn_kernel<<<(unsigned)((n + 255) / 256), 256>>>(g, resid, out, ch, HW);
}

extern "C" void kernel_launch(void* const* d_in, const int* in_sizes, int n_in,
                              void* d_out, int out_size)
{
    (void)in_sizes; (void)n_in; (void)out_size;
    const float* x    = (const float*)d_in[0];
    const float* fe_w = (const float*)d_in[1];  const float* fe_b = (const float*)d_in[2];
    const float* e0_w = (const float*)d_in[3];  const float* e0_b = (const float*)d_in[4];
    const float* e1_w = (const float*)d_in[5];  const float* e1_b = (const float*)d_in[6];
    const float* e2_w = (const float*)d_in[7];  const float* e2_b = (const float*)d_in[8];
    const float* e3_w = (const float*)d_in[9];  const float* e3_b = (const float*)d_in[10];
    const float* e4_w = (const float*)d_in[11]; const float* e4_b = (const float*)d_in[12];
    const float* d0_w = (const float*)d_in[13]; const float* d0_b = (const float*)d_in[14];
    const float* d1_w = (const float*)d_in[15]; const float* d1_b = (const float*)d_in[16];
    const float* d2_w = (const float*)d_in[17]; const float* d2_b = (const float*)d_in[18];
    const float* d3_w = (const float*)d_in[19]; const float* d3_b = (const float*)d_in[20];
    const float* d4_w = (const float*)d_in[21]; const float* d4_b = (const float*)d_in[22];
    const float* rc_w = (const float*)d_in[23]; const float* rc_b = (const float*)d_in[24];

    void* bp = nullptr;
    cudaGetSymbolAddress(&bp, g_buf);
    float* B = (float*)bp;

    float* conv = B + O_CONV;
    float* fe   = B + O_FE;   float* e0 = B + O_E0;
    float* e1   = B + O_E1;   float* e2 = B + O_E2;
    float* e3   = B + O_E3;   float* e4 = B + O_E4;
    float* d0   = B + O_D0;   float* up1 = B + O_UP1;
    float* d1   = B + O_D1;   float* tmp1 = B + O_TMP1;
    float* d2   = B + O_D2;   float* up0 = B + O_UP0;
    float* d3   = B + O_D3;   float* d4 = B + O_D4;

    const long long HW0 = 256LL * 256, HW1 = 128LL * 128, HW2 = 64LL * 64;

    conv_l<4, 1, 0>(x, fe_w, fe_b, conv, 1, 48, 256, 256);
    biqrnn_l(conv, nullptr, fe, 16, HW0);

    conv_l<4, 1, 0>(fe, e0_w, e0_b, conv, 16, 32, 256, 256);
    qrnn_l(conv, e0, 16, HW0, 0);

    conv_l<4, 2, 0>(e0, e1_w, e1_b, conv, 16, 64, 256, 256);
    qrnn_l(conv, e1, 32, HW1, 1);

    conv_l<4, 1, 0>(e1, e2_w, e2_b, conv, 32, 64, 128, 128);
    qrnn_l(conv, e2, 32, HW1, 0);

    conv_l<4, 2, 0>(e2, e3_w, e3_b, conv, 32, 128, 128, 128);
    qrnn_l(conv, e3, 64, HW2, 1);

    conv_l<4, 1, 0>(e3, e4_w, e4_b, conv, 64, 128, 64, 64);
    qrnn_l(conv, e4, 64, HW2, 0);

    conv_l<4, 1, 1>(e4, d0_w, d0_b, conv, 64, 128, 64, 64);
    qrnn_l(conv, d0, 64, HW2, 1);

    {
        long long n4 = 64LL * DZ * 4 * HW2 / 4;
        upadd_kernel<<<(unsigned)((n4 + 255) / 256), 256>>>(d0, e3, up1, 64, 64, 64);
    }
    conv_l<4, 1, 0>(up1, d1_w, d1_b, conv, 64, 64, 128, 128);
    qrnn_l(conv, d1, 32, HW1, 0);

    {
        long long n4 = 32LL * DZ * HW1 / 4;
        add_kernel<<<(unsigned)((n4 + 255) / 256), 256>>>(d1, e2, tmp1, n4);
    }
    conv_l<4, 1, 1>(tmp1, d2_w, d2_b, conv, 32, 64, 128, 128);
    qrnn_l(conv, d2, 32, HW1, 1);

    {
        long long n4 = 32LL * DZ * 4 * HW1 / 4;
        upadd_kernel<<<(unsigned)((n4 + 255) / 256), 256>>>(d2, e1, up0, 32, 128, 128);
    }
    conv_l<4, 1, 0>(up0, d3_w, d3_b, conv, 32, 32, 256, 256);
    qrnn_l(conv, d3, 16, HW0, 0);

    {
        long long n4 = 16LL * DZ * HW0 / 4;
        add_kernel<<<(unsigned)((n4 + 255) / 256), 256>>>(d3, e0, up0, n4);
    }
    conv_l<4, 1, 1>(up0, d4_w, d4_b, conv, 16, 32, 256, 256);
    qrnn_l(conv, d4, 16, HW0, 1);

    {
        long long n4 = 16LL * DZ * HW0 / 4;
        add_kernel<<<(unsigned)((n4 + 255) / 256), 256>>>(d4, fe, up0, n4);
    }
    conv_l<3, 1, 1>(up0, rc_w, rc_b, conv, 16, 3, 256, 256);
    biqrnn_l(conv, x, (float*)d_out, 1, HW0);
}

// round 3
// speedup vs baseline: 1.3405x; 1.3405x over previous
#include <cuda_runtime.h>
#include <math.h>

#define DZ 31

static constexpr long long S0  = 31LL * 256 * 256;
static constexpr long long S1  = 31LL * 128 * 128;
static constexpr long long S2L = 31LL * 64 * 64;

static constexpr long long O_CONV = 0;
static constexpr long long O_FE   = O_CONV + 48 * S0;
static constexpr long long O_E0   = O_FE   + 16 * S0;
static constexpr long long O_E1   = O_E0   + 16 * S0;
static constexpr long long O_E2   = O_E1   + 32 * S1;
static constexpr long long O_E3   = O_E2   + 32 * S1;
static constexpr long long O_E4   = O_E3   + 64 * S2L;
static constexpr long long O_D0   = O_E4   + 64 * S2L;
static constexpr long long O_UP1  = O_D0   + 64 * S2L;
static constexpr long long O_D1   = O_UP1  + 64 * S1;
static constexpr long long O_TMP1 = O_D1   + 32 * S1;
static constexpr long long O_D2   = O_TMP1 + 32 * S1;
static constexpr long long O_UP0  = O_D2   + 32 * S1;
static constexpr long long O_D3   = O_UP0  + 32 * S0;
static constexpr long long O_D4   = O_D3   + 16 * S0;
static constexpr long long TOTAL  = O_D4   + 16 * S0;

__device__ float g_buf[TOTAL];

__device__ __forceinline__ float sigm(float x)     { return 1.0f / (1.0f + __expf(-x)); }
__device__ __forceinline__ float tanhfast(float x) { return 2.0f / (1.0f + __expf(-2.0f * x)) - 1.0f; }

__device__ __forceinline__ unsigned smem_u32(const void* p) {
    return (unsigned)__cvta_generic_to_shared(p);
}
__device__ __forceinline__ void cp_async4(unsigned dst, const float* src, bool ok) {
    int sz = ok ? 4 : 0;
    asm volatile("cp.async.ca.shared.global [%0], [%1], 4, %2;" :: "r"(dst), "l"(src), "r"(sz));
}
__device__ __forceinline__ void cp_commit() { asm volatile("cp.async.commit_group;"); }

// ============================================================================
// conv3d 3x3x3 pad 1, H/W stride STRIDE, FLIP=1 -> deconv.
// Block (16, TH). Output tile 32 x TH at one (co-group, d). OX=2 outputs/thread.
// Input staged in ci-chunks of CB channels, double-buffered via cp.async.
// ============================================================================
template <int COPT, int STRIDE, int FLIP, int TH, int CB>
__global__ void conv3d_kernel(const float* __restrict__ in, const float* __restrict__ w,
                              const float* __restrict__ bias, float* __restrict__ out,
                              int Ci, int Hin, int Win, int Hout, int Wout)
{
    constexpr int TW  = 32, OX = 2;
    constexpr int NT  = 16 * TH;
    constexpr int IW0 = TW * STRIDE + 2;
    constexpr int IW  = (IW0 + 3) & ~3;        // 36 (s1) / 68 (s2)
    constexpr int IH  = TH * STRIDE + 2;       // 18 (both)
    constexpr int CH_SZ = 3 * IH * IW;
    constexpr int BUF   = CB * CH_SZ;

    extern __shared__ float sm[];
    float* s_w  = sm;                          // Ci*27*COPT
    float* s_b0 = sm + Ci * 27 * COPT;
    float* s_b1 = s_b0 + BUF;

    const int tx  = threadIdx.x, ty = threadIdx.y;
    const int tid = ty * 16 + tx;
    const int d   = blockIdx.z % DZ;
    const int co0 = (blockIdx.z / DZ) * COPT;
    const int ox0 = blockIdx.x * TW;
    const int oy0 = blockIdx.y * TH;
    const int gx0 = ox0 * STRIDE - 1;
    const int gy0 = oy0 * STRIDE - 1;
    const int HWin = Hin * Win;

    // stage all weights once (transposed: co fastest)
    const int WCNT = Ci * 27 * COPT;
    for (int t = tid; t < WCNT; t += NT) {
        int j  = t % COPT;
        int r  = t / COPT;
        int k  = r % 27;
        int ci = r / 27;
        int kk = FLIP ? (26 - k) : k;
        s_w[t] = w[((long long)(co0 + j) * Ci + ci) * 27 + kk];
    }

    float acc[OX][COPT];
#pragma unroll
    for (int x = 0; x < OX; x++)
#pragma unroll
        for (int j = 0; j < COPT; j++) acc[x][j] = bias[co0 + j];

    // async staging of one CB-channel chunk
    auto stage = [&](float* buf, int ci0) {
        for (int t = tid; t < BUF; t += NT) {
            int cc = t / CH_SZ;
            int r  = t % CH_SZ;
            int kd = r / (IH * IW);
            int rr = (r / IW) % IH;
            int c2 = r % IW;
            int ci = ci0 + cc;
            int gz = d - 1 + kd;
            int gy = gy0 + rr;
            int gx = gx0 + c2;
            bool ok = (ci < Ci) && (gz >= 0) && (gz < DZ) &&
                      ((unsigned)gy < (unsigned)Hin) && ((unsigned)gx < (unsigned)Win);
            const float* src = ok ? (in + ((long long)(ci * DZ + gz) * HWin + gy * Win + gx)) : in;
            cp_async4(smem_u32(buf + t), src, ok);
        }
        cp_commit();
    };

    const int nch = (Ci + CB - 1) / CB;
    stage(s_b0, 0);

    for (int c = 0; c < nch; c++) {
        float* cur = (c & 1) ? s_b1 : s_b0;
        float* nxt = (c & 1) ? s_b0 : s_b1;
        if (c + 1 < nch) {
            stage(nxt, (c + 1) * CB);
            asm volatile("cp.async.wait_group 1;");
        } else {
            asm volatile("cp.async.wait_group 0;");
        }
        __syncthreads();

        const int cb_lim = min(CB, Ci - c * CB);
        for (int cc = 0; cc < cb_lim; cc++) {
            const float* sin = cur + cc * CH_SZ;
            const float* swc = s_w + (c * CB + cc) * 27 * COPT;
#pragma unroll
            for (int kd = 0; kd < 3; kd++) {
#pragma unroll
                for (int kh = 0; kh < 3; kh++) {
                    const float* row = sin + (kd * IH + ty * STRIDE + kh) * IW + tx * (OX * STRIDE);
                    float vv[OX * STRIDE + 2];
                    if (STRIDE == 1) {
                        float2 a = *reinterpret_cast<const float2*>(row);
                        float2 b = *reinterpret_cast<const float2*>(row + 2);
                        vv[0] = a.x; vv[1] = a.y; vv[2] = b.x; vv[3] = b.y;
                    } else {
                        float4 a = *reinterpret_cast<const float4*>(row);
                        vv[0] = a.x; vv[1] = a.y; vv[2] = a.z; vv[3] = a.w; vv[4] = row[4];
                    }
#pragma unroll
                    for (int kw = 0; kw < 3; kw++) {
                        const int k = (kd * 3 + kh) * 3 + kw;
                        if (COPT == 4) {
                            float4 w4 = *reinterpret_cast<const float4*>(swc + k * 4);
#pragma unroll
                            for (int x = 0; x < OX; x++) {
                                float v = vv[x * STRIDE + kw];
                                acc[x][0] += v * w4.x;
                                acc[x][1] += v * w4.y;
                                acc[x][2] += v * w4.z;
                                acc[x][3] += v * w4.w;
                            }
                        } else {
#pragma unroll
                            for (int j = 0; j < COPT; j++) {
                                float wj = swc[k * COPT + j];
#pragma unroll
                                for (int x = 0; x < OX; x++)
                                    acc[x][j] += vv[x * STRIDE + kw] * wj;
                            }
                        }
                    }
                }
            }
        }
        __syncthreads();
    }

    const long long HWout = (long long)Hout * Wout;
    const int oy  = oy0 + ty;
    const int oxb = ox0 + tx * OX;
#pragma unroll
    for (int j = 0; j < COPT; j++) {
        float2 v2 = make_float2(acc[0][j], acc[1][j]);
        *reinterpret_cast<float2*>(out + ((long long)(co0 + j) * DZ + d) * HWout +
                                   (long long)oy * Wout + oxb) = v2;
    }
}

// ============================================================================
// fo_pool (QRNN): gates [2*ch][DZ][HW]. float2 per thread.
// ============================================================================
__global__ void qrnn_kernel(const float* __restrict__ g, float* __restrict__ out,
                            int ch, long long HW, int reverse)
{
    long long H2 = HW / 2;
    long long idx = (long long)blockIdx.x * blockDim.x + threadIdx.x;
    if (idx >= (long long)ch * H2) return;
    int c = (int)(idx / H2);
    long long p = (idx % H2);
    const float2* zp = reinterpret_cast<const float2*>(g + (long long)c * DZ * HW) + p;
    const float2* fp = reinterpret_cast<const float2*>(g + (long long)(ch + c) * DZ * HW) + p;
    float2* op = reinterpret_cast<float2*>(out + (long long)c * DZ * HW) + p;
    float hx = 0.0f, hy = 0.0f;
    if (!reverse) {
        for (int t = 0; t < DZ; t++) {
            float2 z2 = zp[t * H2];
            float2 f2 = fp[t * H2];
            float fx = sigm(f2.x), fy = sigm(f2.y);
            hx = fx * hx + (1.0f - fx) * tanhfast(z2.x);
            hy = fy * hy + (1.0f - fy) * tanhfast(z2.y);
            op[t * H2] = make_float2(hx, hy);
        }
    } else {
        for (int t = DZ - 1; t >= 0; t--) {
            float2 z2 = zp[t * H2];
            float2 f2 = fp[t * H2];
            float fx = sigm(f2.x), fy = sigm(f2.y);
            hx = fx * hx + (1.0f - fx) * tanhfast(z2.x);
            hy = fy * hy + (1.0f - fy) * tanhfast(z2.y);
            op[t * H2] = make_float2(hx, hy);
        }
    }
}

__global__ void biqrnn_kernel(const float* __restrict__ g, const float* __restrict__ resid,
                              float* __restrict__ out, int ch, long long HW)
{
    long long H2 = HW / 2;
    long long idx = (long long)blockIdx.x * blockDim.x + threadIdx.x;
    if (idx >= (long long)ch * H2) return;
    int c = (int)(idx / H2);
    long long p = (idx % H2);
    const float2* zp = reinterpret_cast<const float2*>(g + (long long)c * DZ * HW) + p;
    const float2* f1 = reinterpret_cast<const float2*>(g + (long long)(ch + c) * DZ * HW) + p;
    const float2* f2 = reinterpret_cast<const float2*>(g + (long long)(2 * ch + c) * DZ * HW) + p;
    float2* op = reinterpret_cast<float2*>(out + (long long)c * DZ * HW) + p;
    const float2* rp = resid ? (reinterpret_cast<const float2*>(resid + (long long)c * DZ * HW) + p)
                             : nullptr;
    float hx = 0.0f, hy = 0.0f;
    for (int t = 0; t < DZ; t++) {
        float2 z2 = zp[t * H2];
        float2 ff = f1[t * H2];
        float fx = sigm(ff.x), fy = sigm(ff.y);
        hx = fx * hx + (1.0f - fx) * tanhfast(z2.x);
        hy = fy * hy + (1.0f - fy) * tanhfast(z2.y);
        op[t * H2] = make_float2(hx, hy);
    }
    hx = 0.0f; hy = 0.0f;
    for (int t = DZ - 1; t >= 0; t--) {
        float2 z2 = zp[t * H2];
        float2 ff = f2[t * H2];
        float fx = sigm(ff.x), fy = sigm(ff.y);
        hx = fx * hx + (1.0f - fx) * tanhfast(z2.x);
        hy = fy * hy + (1.0f - fy) * tanhfast(z2.y);
        float2 cur = op[t * H2];
        float rx = 0.0f, ry = 0.0f;
        if (rp) { float2 r2 = rp[t * H2]; rx = r2.x; ry = r2.y; }
        op[t * H2] = make_float2(cur.x + hx + rx, cur.y + hy + ry);
    }
}

__global__ void upadd_kernel(const float* __restrict__ a, const float* __restrict__ b,
                             float* __restrict__ out, int ch, int Hs, int Ws)
{
    long long N4 = (long long)ch * DZ * 4LL * Hs * Ws / 4;
    long long i = (long long)blockIdx.x * blockDim.x + threadIdx.x;
    if (i >= N4) return;
    int Wd4 = (2 * Ws) / 4;
    int x4 = (int)(i % Wd4);
    long long r = i / Wd4;
    int y = (int)(r % (2 * Hs));
    r /= (2 * Hs);
    long long src = r * ((long long)Hs * Ws) + (long long)(y >> 1) * Ws + x4 * 2;
    float2 av = *reinterpret_cast<const float2*>(a + src);
    float2 bv = *reinterpret_cast<const float2*>(b + src);
    float sx = av.x + bv.x, sy = av.y + bv.y;
    reinterpret_cast<float4*>(out)[i] = make_float4(sx, sx, sy, sy);
}

__global__ void add_kernel(const float* __restrict__ a, const float* __restrict__ b,
                           float* __restrict__ o, long long n4)
{
    long long i = (long long)blockIdx.x * blockDim.x + threadIdx.x;
    if (i >= n4) return;
    float4 av = reinterpret_cast<const float4*>(a)[i];
    float4 bv = reinterpret_cast<const float4*>(b)[i];
    reinterpret_cast<float4*>(o)[i] = make_float4(av.x + bv.x, av.y + bv.y, av.z + bv.z, av.w + bv.w);
}

// ============================================================================
// Host launchers
// ============================================================================
template <int COPT, int STRIDE, int FLIP>
static void conv_l(const float* in, const float* w, const float* b, float* out,
                   int Ci, int Co, int Hin, int Win)
{
    constexpr int TH = (STRIDE == 1) ? 16 : 8;
    constexpr int CB = (STRIDE == 1) ? 4 : 2;
    constexpr int TW = 32;
    constexpr int IW = ((TW * STRIDE + 2) + 3) & ~3;
    constexpr int IH = TH * STRIDE + 2;
    constexpr int BUF = CB * 3 * IH * IW;
    int Hout = Hin / STRIDE, Wout = Win / STRIDE;
    dim3 grid(Wout / TW, Hout / TH, (Co / COPT) * DZ);
    size_t smem = (size_t)(Ci * 27 * COPT + 2 * BUF) * sizeof(float);
    cudaFuncSetAttribute(conv3d_kernel<COPT, STRIDE, FLIP, TH, CB>,
                         cudaFuncAttributeMaxDynamicSharedMemorySize, (int)smem);
    conv3d_kernel<COPT, STRIDE, FLIP, TH, CB><<<grid, dim3(16, TH), smem>>>(
        in, w, b, out, Ci, Hin, Win, Hout, Wout);
}

static void qrnn_l(const float* g, float* out, int ch, long long HW, int reverse)
{
    long long n = (long long)ch * HW / 2;
    qrnn_kernel<<<(unsigned)((n + 255) / 256), 256>>>(g, out, ch, HW, reverse);
}

static void biqrnn_l(const float* g, const float* resid, float* out, int ch, long long HW)
{
    long long n = (long long)ch * HW / 2;
    biqrnn_kernel<<<(unsigned)((n + 255) / 256), 256>>>(g, resid, out, ch, HW);
}

extern "C" void kernel_launch(void* const* d_in, const int* in_sizes, int n_in,
                              void* d_out, int out_size)
{
    (void)in_sizes; (void)n_in; (void)out_size;
    const float* x    = (const float*)d_in[0];
    const float* fe_w = (const float*)d_in[1];  const float* fe_b = (const float*)d_in[2];
    const float* e0_w = (const float*)d_in[3];  const float* e0_b = (const float*)d_in[4];
    const float* e1_w = (const float*)d_in[5];  const float* e1_b = (const float*)d_in[6];
    const float* e2_w = (const float*)d_in[7];  const float* e2_b = (const float*)d_in[8];
    const float* e3_w = (const float*)d_in[9];  const float* e3_b = (const float*)d_in[10];
    const float* e4_w = (const float*)d_in[11]; const float* e4_b = (const float*)d_in[12];
    const float* d0_w = (const float*)d_in[13]; const float* d0_b = (const float*)d_in[14];
    const float* d1_w = (const float*)d_in[15]; const float* d1_b = (const float*)d_in[16];
    const float* d2_w = (const float*)d_in[17]; const float* d2_b = (const float*)d_in[18];
    const float* d3_w = (const float*)d_in[19]; const float* d3_b = (const float*)d_in[20];
    const float* d4_w = (const float*)d_in[21]; const float* d4_b = (const float*)d_in[22];
    const float* rc_w = (const float*)d_in[23]; const float* rc_b = (const float*)d_in[24];

    void* bp = nullptr;
    cudaGetSymbolAddress(&bp, g_buf);
    float* B = (float*)bp;

    float* conv = B + O_CONV;
    float* fe   = B + O_FE;   float* e0 = B + O_E0;
    float* e1   = B + O_E1;   float* e2 = B + O_E2;
    float* e3   = B + O_E3;   float* e4 = B + O_E4;
    float* d0   = B + O_D0;   float* up1 = B + O_UP1;
    float* d1   = B + O_D1;   float* tmp1 = B + O_TMP1;
    float* d2   = B + O_D2;   float* up0 = B + O_UP0;
    float* d3   = B + O_D3;   float* d4 = B + O_D4;

    const long long HW0 = 256LL * 256, HW1 = 128LL * 128, HW2 = 64LL * 64;

    conv_l<4, 1, 0>(x, fe_w, fe_b, conv, 1, 48, 256, 256);
    biqrnn_l(conv, nullptr, fe, 16, HW0);

    conv_l<4, 1, 0>(fe, e0_w, e0_b, conv, 16, 32, 256, 256);
    qrnn_l(conv, e0, 16, HW0, 0);

    conv_l<4, 2, 0>(e0, e1_w, e1_b, conv, 16, 64, 256, 256);
    qrnn_l(conv, e1, 32, HW1, 1);

    conv_l<4, 1, 0>(e1, e2_w, e2_b, conv, 32, 64, 128, 128);
    qrnn_l(conv, e2, 32, HW1, 0);

    conv_l<4, 2, 0>(e2, e3_w, e3_b, conv, 32, 128, 128, 128);
    qrnn_l(conv, e3, 64, HW2, 1);

    conv_l<4, 1, 0>(e3, e4_w, e4_b, conv, 64, 128, 64, 64);
    qrnn_l(conv, e4, 64, HW2, 0);

    conv_l<4, 1, 1>(e4, d0_w, d0_b, conv, 64, 128, 64, 64);
    qrnn_l(conv, d0, 64, HW2, 1);

    {
        long long n4 = 64LL * DZ * 4 * HW2 / 4;
        upadd_kernel<<<(unsigned)((n4 + 255) / 256), 256>>>(d0, e3, up1, 64, 64, 64);
    }
    conv_l<4, 1, 0>(up1, d1_w, d1_b, conv, 64, 64, 128, 128);
    qrnn_l(conv, d1, 32, HW1, 0);

    {
        long long n4 = 32LL * DZ * HW1 / 4;
        add_kernel<<<(unsigned)((n4 + 255) / 256), 256>>>(d1, e2, tmp1, n4);
    }
    conv_l<4, 1, 1>(tmp1, d2_w, d2_b, conv, 32, 64, 128, 128);
    qrnn_l(conv, d2, 32, HW1, 1);

    {
        long long n4 = 32LL * DZ * 4 * HW1 / 4;
        upadd_kernel<<<(unsigned)((n4 + 255) / 256), 256>>>(d2, e1, up0, 32, 128, 128);
    }
    conv_l<4, 1, 0>(up0, d3_w, d3_b, conv, 32, 32, 256, 256);
    qrnn_l(conv, d3, 16, HW0, 0);

    {
        long long n4 = 16LL * DZ * HW0 / 4;
        add_kernel<<<(unsigned)((n4 + 255) / 256), 256>>>(d3, e0, up0, n4);
    }
    conv_l<4, 1, 1>(up0, d4_w, d4_b, conv, 16, 32, 256, 256);
    qrnn_l(conv, d4, 16, HW0, 1);

    {
        long long n4 = 16LL * DZ * HW0 / 4;
        add_kernel<<<(unsigned)((n4 + 255) / 256), 256>>>(d4, fe, up0, n4);
    }
    conv_l<3, 1, 1>(up0, rc_w, rc_b, conv, 16, 3, 256, 256);
    biqrnn_l(conv, x, (float*)d_out, 1, HW0);
}